// round 3
// baseline (speedup 1.0000x reference)
#include <cuda_runtime.h>
#include <math.h>

// Problem constants (fixed by the dataset; guarded at runtime anyway)
#define NMAX   100032
#define DIMF   128        // feature dim = hidden dim
#define DV4    32         // DIMF/4

// Static scratch (no allocation allowed in kernel_launch)
__device__ float g_scaled[NMAX * DIMF];
__device__ float g_agg[NMAX * DIMF];
__device__ float g_x[NMAX * DIMF];
__device__ float g_csrc[NMAX];
__device__ float g_cdst[NMAX];
__device__ int   g_deg[2 * NMAX];

// ---------------------------------------------------------------------------
// Degree computation: deg includes the self loop (init 1), then +1 per edge.
// g_deg[0..n)   = out-degree (indexed by src)
// g_deg[n..2n)  = in-degree  (indexed by dst)
// ---------------------------------------------------------------------------
__global__ void k_deg_init(int n) {
    int i = blockIdx.x * blockDim.x + threadIdx.x;
    if (i < 2 * n) g_deg[i] = 1;
}

__global__ void k_deg_count(const int* __restrict__ ei, int E, int n) {
    int i = blockIdx.x * blockDim.x + threadIdx.x;
    if (i < E) {
        atomicAdd(&g_deg[ei[i]], 1);          // src -> out-degree
        atomicAdd(&g_deg[n + ei[E + i]], 1);  // dst -> in-degree
    }
}

__global__ void k_coef(int n) {
    int i = blockIdx.x * blockDim.x + threadIdx.x;
    if (i < n) {
        g_csrc[i] = rsqrtf((float)g_deg[i]);
        g_cdst[i] = rsqrtf((float)g_deg[n + i]);
    }
}

// ---------------------------------------------------------------------------
// scaled = x * c_src[row];  agg = scaled  (agg init == self-loop contribution)
// One thread per float4.
// ---------------------------------------------------------------------------
__global__ void k_scale(const float* __restrict__ x, int n) {
    int idx = blockIdx.x * blockDim.x + threadIdx.x;
    if (idx < n * DV4) {
        int row = idx >> 5;
        float c = g_csrc[row];
        float4 v = ((const float4*)x)[idx];
        v.x *= c; v.y *= c; v.z *= c; v.w *= c;
        ((float4*)g_scaled)[idx] = v;
        ((float4*)g_agg)[idx]    = v;
    }
}

// ---------------------------------------------------------------------------
// Scatter: for each edge (s,d): agg[d,:] += scaled[s,:]
// One warp per edge; each lane handles one float4 (coalesced 512B per row).
// red.global.add.v4.f32 = no-return vector reduction (sm_90+).
// ---------------------------------------------------------------------------
__global__ void k_scatter(const int* __restrict__ ei, int E) {
    int idx = blockIdx.x * blockDim.x + threadIdx.x;
    if (idx < E * DV4) {
        int e = idx >> 5;
        int c = idx & 31;
        int s = __ldg(&ei[e]);
        int d = __ldg(&ei[E + e]);
        float4 v = ((const float4*)g_scaled)[s * DV4 + c];
        float4* p = ((float4*)g_agg) + d * DV4 + c;
        asm volatile("red.global.add.v4.f32 [%0], {%1,%2,%3,%4};"
                     :: "l"(p), "f"(v.x), "f"(v.y), "f"(v.z), "f"(v.w)
                     : "memory");
    }
}

// ---------------------------------------------------------------------------
// GEMM: out[r, :] = relu?( (agg[r,:] * c_dst[r]) @ W + b )
// 64 rows per block, 128 threads, each thread computes 8 rows x 8 cols.
// Full K=128 staged through smem in 8 chunks of 16 k-rows.
// ---------------------------------------------------------------------------
template <bool RELU>
__global__ void k_gemm(const float* __restrict__ W, const float* __restrict__ b,
                       float* __restrict__ out, int n) {
    __shared__ float x_s[64][DIMF + 1];   // +1 pad: kill row-stride bank conflicts
    __shared__ float w_s[16][DIMF];

    const int tid = threadIdx.x;          // 128 threads
    const int tx  = tid & 15;             // col group: cols tx*8 .. tx*8+7
    const int ty  = tid >> 4;             // row group: rows ty, ty+8, ..., ty+56
    const int rowBase = blockIdx.x * 64;

    // Load x tile = agg * c_dst (zeros past n)
    for (int f = tid; f < 64 * DV4; f += 128) {
        int r  = f >> 5;
        int c4 = f & 31;
        int gr = rowBase + r;
        float4 v = make_float4(0.f, 0.f, 0.f, 0.f);
        if (gr < n) {
            v = ((const float4*)g_agg)[gr * DV4 + c4];
            float cd = g_cdst[gr];
            v.x *= cd; v.y *= cd; v.z *= cd; v.w *= cd;
        }
        x_s[r][c4 * 4 + 0] = v.x;
        x_s[r][c4 * 4 + 1] = v.y;
        x_s[r][c4 * 4 + 2] = v.z;
        x_s[r][c4 * 4 + 3] = v.w;
    }

    // Accumulators init to bias
    float4 bv0 = ((const float4*)b)[tx * 2];
    float4 bv1 = ((const float4*)b)[tx * 2 + 1];
    float acc[8][8];
#pragma unroll
    for (int rr = 0; rr < 8; rr++) {
        acc[rr][0] = bv0.x; acc[rr][1] = bv0.y; acc[rr][2] = bv0.z; acc[rr][3] = bv0.w;
        acc[rr][4] = bv1.x; acc[rr][5] = bv1.y; acc[rr][6] = bv1.z; acc[rr][7] = bv1.w;
    }

    for (int kc = 0; kc < 8; kc++) {
        __syncthreads();  // previous chunk consumed (and x_s load done on first iter)
        // Load 16 k-rows of W
        for (int f = tid; f < 16 * DV4; f += 128) {
            int kk = f >> 5;
            int c4 = f & 31;
            ((float4*)&w_s[kk][0])[c4] =
                ((const float4*)W)[(kc * 16 + kk) * DV4 + c4];
        }
        __syncthreads();

#pragma unroll
        for (int kk = 0; kk < 16; kk++) {
            float4 w0 = *(const float4*)&w_s[kk][tx * 8];
            float4 w1 = *(const float4*)&w_s[kk][tx * 8 + 4];
#pragma unroll
            for (int rr = 0; rr < 8; rr++) {
                float xv = x_s[ty + rr * 8][kc * 16 + kk];
                acc[rr][0] += xv * w0.x; acc[rr][1] += xv * w0.y;
                acc[rr][2] += xv * w0.z; acc[rr][3] += xv * w0.w;
                acc[rr][4] += xv * w1.x; acc[rr][5] += xv * w1.y;
                acc[rr][6] += xv * w1.z; acc[rr][7] += xv * w1.w;
            }
        }
    }

#pragma unroll
    for (int rr = 0; rr < 8; rr++) {
        int gr = rowBase + ty + rr * 8;
        if (gr < n) {
            float4 o0 = make_float4(acc[rr][0], acc[rr][1], acc[rr][2], acc[rr][3]);
            float4 o1 = make_float4(acc[rr][4], acc[rr][5], acc[rr][6], acc[rr][7]);
            if (RELU) {
                o0.x = fmaxf(o0.x, 0.f); o0.y = fmaxf(o0.y, 0.f);
                o0.z = fmaxf(o0.z, 0.f); o0.w = fmaxf(o0.w, 0.f);
                o1.x = fmaxf(o1.x, 0.f); o1.y = fmaxf(o1.y, 0.f);
                o1.z = fmaxf(o1.z, 0.f); o1.w = fmaxf(o1.w, 0.f);
            }
            ((float4*)&out[gr * DIMF + tx * 8])[0] = o0;
            ((float4*)&out[gr * DIMF + tx * 8 + 4])[0] = o1;
        }
    }
}

// ---------------------------------------------------------------------------

static inline int cdiv(int a, int b) { return (a + b - 1) / b; }

static void run_layer(const float* x, const float* W, const float* b,
                      float* out, const int* edge, int n, int E, bool relu) {
    k_scale<<<cdiv(n * DV4, 256), 256>>>(x, n);
    k_scatter<<<cdiv(E * DV4, 256), 256>>>(edge, E);
    if (relu) k_gemm<true><<<cdiv(n, 64), 128>>>(W, b, out, n);
    else      k_gemm<false><<<cdiv(n, 64), 128>>>(W, b, out, n);
}

extern "C" void kernel_launch(void* const* d_in, const int* in_sizes, int n_in,
                              void* d_out, int out_size) {
    const float* node_attr = (const float*)d_in[0];
    const float* W0 = (const float*)d_in[1];
    const float* b0 = (const float*)d_in[2];
    const float* W1 = (const float*)d_in[3];
    const float* b1 = (const float*)d_in[4];
    const float* W2 = (const float*)d_in[5];
    const float* b2 = (const float*)d_in[6];
    const int*   edge = (const int*)d_in[7];

    int n = in_sizes[0] / DIMF;   // 100000
    int E = in_sizes[7] / 2;      // 1600000

    float* xbuf;
    cudaGetSymbolAddress((void**)&xbuf, g_x);

    // degrees + normalization coefficients
    k_deg_init<<<cdiv(2 * n, 256), 256>>>(n);
    k_deg_count<<<cdiv(E, 256), 256>>>(edge, E, n);
    k_coef<<<cdiv(n, 256), 256>>>(n);

    // 3 GCN layers
    run_layer(node_attr, W0, b0, xbuf, edge, n, E, true);
    run_layer(xbuf,      W1, b1, xbuf, edge, n, E, true);
    run_layer(xbuf,      W2, b2, (float*)d_out, edge, n, E, false);
}

// round 4
// speedup vs baseline: 1.6481x; 1.6481x over previous
#include <cuda_runtime.h>
#include <math.h>

// Problem constants (fixed by the dataset)
#define NMAX   100032
#define EMAX   1600000
#define DIMF   128        // feature dim = hidden dim
#define DV4    32         // DIMF/4
#define SCANB  1024
#define NSCANB ((NMAX + SCANB - 1) / SCANB)

// Static scratch (no allocation allowed)
__device__ float g_scaled[NMAX * DIMF];
__device__ float g_agg[NMAX * DIMF];
__device__ float g_csrc[NMAX];
__device__ float g_cdst[NMAX];
__device__ int   g_deg[2 * NMAX];     // [0..n) out-deg(+self), [n..2n) in-deg(+self)
__device__ int   g_off[NMAX + 1];     // CSR row offsets (by dst)
__device__ int   g_cursor[NMAX];      // fill cursors
__device__ int   g_csr_src[EMAX];     // CSR: src ids grouped by dst
__device__ int   g_bsum[NSCANB];      // scan block sums

static inline int cdiv(int a, int b) { return (a + b - 1) / b; }

// ---------------------------------------------------------------------------
// Degrees (self-loop included via init=1) and normalization coefficients
// ---------------------------------------------------------------------------
__global__ void k_deg_init(int n) {
    int i = blockIdx.x * blockDim.x + threadIdx.x;
    if (i < 2 * n) g_deg[i] = 1;
}

__global__ void k_deg_count(const int* __restrict__ ei, int E, int n) {
    int i = blockIdx.x * blockDim.x + threadIdx.x;
    if (i < E) {
        atomicAdd(&g_deg[ei[i]], 1);          // src -> out-degree
        atomicAdd(&g_deg[n + ei[E + i]], 1);  // dst -> in-degree
    }
}

__global__ void k_coef(int n) {
    int i = blockIdx.x * blockDim.x + threadIdx.x;
    if (i < n) {
        g_csrc[i] = rsqrtf((float)g_deg[i]);
        g_cdst[i] = rsqrtf((float)g_deg[n + i]);
    }
}

// ---------------------------------------------------------------------------
// CSR build: exclusive scan of raw in-degree (= g_deg[n+i]-1), then fill.
// ---------------------------------------------------------------------------
__global__ void k_scan1(int n) {
    __shared__ int sh[SCANB];
    int t = threadIdx.x;
    int i = blockIdx.x * SCANB + t;
    int v = (i < n) ? (g_deg[n + i] - 1) : 0;
    sh[t] = v;
    __syncthreads();
#pragma unroll
    for (int o = 1; o < SCANB; o <<= 1) {
        int add = (t >= o) ? sh[t - o] : 0;
        __syncthreads();
        sh[t] += add;
        __syncthreads();
    }
    if (i < n) g_off[i] = sh[t] - v;          // exclusive within block
    if (t == SCANB - 1) g_bsum[blockIdx.x] = sh[t];
}

__global__ void k_scan2(int n, int nb) {
    // single thread: tiny (nb <= 98)
    int run = 0;
    for (int b = 0; b < nb; b++) {
        int s = g_bsum[b];
        g_bsum[b] = run;
        run += s;
    }
    g_off[n] = run;   // == E
}

__global__ void k_scan3(int n) {
    int i = blockIdx.x * SCANB + threadIdx.x;
    if (i < n) {
        int o = g_off[i] + g_bsum[blockIdx.x];
        g_off[i] = o;
        g_cursor[i] = o;
    }
}

__global__ void k_fill(const int* __restrict__ ei, int E) {
    int i = blockIdx.x * blockDim.x + threadIdx.x;
    if (i < E) {
        int s = ei[i];
        int d = ei[E + i];
        int pos = atomicAdd(&g_cursor[d], 1);
        g_csr_src[pos] = s;
    }
}

// ---------------------------------------------------------------------------
// Layer-1 scale: scaled = node_attr * c_src[row]
// ---------------------------------------------------------------------------
__global__ void k_scale(const float* __restrict__ x, int n) {
    int idx = blockIdx.x * blockDim.x + threadIdx.x;
    if (idx < n * DV4) {
        int row = idx >> 5;
        float c = g_csrc[row];
        float4 v = ((const float4*)x)[idx];
        v.x *= c; v.y *= c; v.z *= c; v.w *= c;
        ((float4*)g_scaled)[idx] = v;
    }
}

// ---------------------------------------------------------------------------
// Gather-sum (replaces atomic scatter):
//   agg[d,:] = scaled[d,:] + sum_{s in in(d)} scaled[s,:]
// One warp per dst node; lane = one float4 column (row = 512B = 1 warp-LDG.128).
// Unroll-by-4 over edges for MLP.
// ---------------------------------------------------------------------------
__global__ void k_gather(int n) {
    int gw = (blockIdx.x * blockDim.x + threadIdx.x) >> 5;  // warp id = node
    int lane = threadIdx.x & 31;
    if (gw >= n) return;

    const float4* sc = (const float4*)g_scaled;
    float4 acc = __ldg(&sc[gw * DV4 + lane]);               // self loop

    int j   = g_off[gw];
    int end = g_off[gw + 1];

    for (; j + 4 <= end; j += 4) {
        int s0 = __ldg(&g_csr_src[j]);
        int s1 = __ldg(&g_csr_src[j + 1]);
        int s2 = __ldg(&g_csr_src[j + 2]);
        int s3 = __ldg(&g_csr_src[j + 3]);
        float4 v0 = __ldg(&sc[s0 * DV4 + lane]);
        float4 v1 = __ldg(&sc[s1 * DV4 + lane]);
        float4 v2 = __ldg(&sc[s2 * DV4 + lane]);
        float4 v3 = __ldg(&sc[s3 * DV4 + lane]);
        acc.x += v0.x + v1.x + v2.x + v3.x;
        acc.y += v0.y + v1.y + v2.y + v3.y;
        acc.z += v0.z + v1.z + v2.z + v3.z;
        acc.w += v0.w + v1.w + v2.w + v3.w;
    }
    for (; j < end; j++) {
        int s = __ldg(&g_csr_src[j]);
        float4 v = __ldg(&sc[s * DV4 + lane]);
        acc.x += v.x; acc.y += v.y; acc.z += v.z; acc.w += v.w;
    }
    ((float4*)g_agg)[gw * DV4 + lane] = acc;
}

// ---------------------------------------------------------------------------
// GEMM: y[r,:] = (agg[r,:] * c_dst[r]) @ W + b
//   WRITE_SCALED: g_scaled[r,:] = relu(y) * c_src[r]   (hidden layers)
//   else:         out[r,:] = y                          (final layer)
// 64 rows/block, 128 threads, 8x8 register tile per thread.
// ---------------------------------------------------------------------------
template <bool WRITE_SCALED>
__global__ void k_gemm(const float* __restrict__ W, const float* __restrict__ b,
                       float* __restrict__ out, int n) {
    __shared__ float x_s[64][DIMF + 1];
    __shared__ float w_s[16][DIMF];

    const int tid = threadIdx.x;
    const int tx  = tid & 15;             // col group: cols tx*8 .. tx*8+7
    const int ty  = tid >> 4;             // rows ty, ty+8, ..., ty+56
    const int rowBase = blockIdx.x * 64;

    for (int f = tid; f < 64 * DV4; f += 128) {
        int r  = f >> 5;
        int c4 = f & 31;
        int gr = rowBase + r;
        float4 v = make_float4(0.f, 0.f, 0.f, 0.f);
        if (gr < n) {
            v = ((const float4*)g_agg)[gr * DV4 + c4];
            float cd = g_cdst[gr];
            v.x *= cd; v.y *= cd; v.z *= cd; v.w *= cd;
        }
        x_s[r][c4 * 4 + 0] = v.x;
        x_s[r][c4 * 4 + 1] = v.y;
        x_s[r][c4 * 4 + 2] = v.z;
        x_s[r][c4 * 4 + 3] = v.w;
    }

    float4 bv0 = ((const float4*)b)[tx * 2];
    float4 bv1 = ((const float4*)b)[tx * 2 + 1];
    float acc[8][8];
#pragma unroll
    for (int rr = 0; rr < 8; rr++) {
        acc[rr][0] = bv0.x; acc[rr][1] = bv0.y; acc[rr][2] = bv0.z; acc[rr][3] = bv0.w;
        acc[rr][4] = bv1.x; acc[rr][5] = bv1.y; acc[rr][6] = bv1.z; acc[rr][7] = bv1.w;
    }

    for (int kc = 0; kc < 8; kc++) {
        __syncthreads();
        for (int f = tid; f < 16 * DV4; f += 128) {
            int kk = f >> 5;
            int c4 = f & 31;
            ((float4*)&w_s[kk][0])[c4] =
                ((const float4*)W)[(kc * 16 + kk) * DV4 + c4];
        }
        __syncthreads();

#pragma unroll
        for (int kk = 0; kk < 16; kk++) {
            float4 w0 = *(const float4*)&w_s[kk][tx * 8];
            float4 w1 = *(const float4*)&w_s[kk][tx * 8 + 4];
#pragma unroll
            for (int rr = 0; rr < 8; rr++) {
                float xv = x_s[ty + rr * 8][kc * 16 + kk];
                acc[rr][0] += xv * w0.x; acc[rr][1] += xv * w0.y;
                acc[rr][2] += xv * w0.z; acc[rr][3] += xv * w0.w;
                acc[rr][4] += xv * w1.x; acc[rr][5] += xv * w1.y;
                acc[rr][6] += xv * w1.z; acc[rr][7] += xv * w1.w;
            }
        }
    }

#pragma unroll
    for (int rr = 0; rr < 8; rr++) {
        int gr = rowBase + ty + rr * 8;
        if (gr < n) {
            float4 o0 = make_float4(acc[rr][0], acc[rr][1], acc[rr][2], acc[rr][3]);
            float4 o1 = make_float4(acc[rr][4], acc[rr][5], acc[rr][6], acc[rr][7]);
            if (WRITE_SCALED) {
                float cs = g_csrc[gr];
                o0.x = fmaxf(o0.x, 0.f) * cs; o0.y = fmaxf(o0.y, 0.f) * cs;
                o0.z = fmaxf(o0.z, 0.f) * cs; o0.w = fmaxf(o0.w, 0.f) * cs;
                o1.x = fmaxf(o1.x, 0.f) * cs; o1.y = fmaxf(o1.y, 0.f) * cs;
                o1.z = fmaxf(o1.z, 0.f) * cs; o1.w = fmaxf(o1.w, 0.f) * cs;
                ((float4*)&g_scaled[gr * DIMF + tx * 8])[0] = o0;
                ((float4*)&g_scaled[gr * DIMF + tx * 8 + 4])[0] = o1;
            } else {
                ((float4*)&out[gr * DIMF + tx * 8])[0] = o0;
                ((float4*)&out[gr * DIMF + tx * 8 + 4])[0] = o1;
            }
        }
    }
}

// ---------------------------------------------------------------------------

extern "C" void kernel_launch(void* const* d_in, const int* in_sizes, int n_in,
                              void* d_out, int out_size) {
    const float* node_attr = (const float*)d_in[0];
    const float* W0 = (const float*)d_in[1];
    const float* b0 = (const float*)d_in[2];
    const float* W1 = (const float*)d_in[3];
    const float* b1 = (const float*)d_in[4];
    const float* W2 = (const float*)d_in[5];
    const float* b2 = (const float*)d_in[6];
    const int*   edge = (const int*)d_in[7];

    int n = in_sizes[0] / DIMF;   // 100000
    int E = in_sizes[7] / 2;      // 1600000
    int nb = cdiv(n, SCANB);

    // degrees + coefficients
    k_deg_init<<<cdiv(2 * n, 256), 256>>>(n);
    k_deg_count<<<cdiv(E, 256), 256>>>(edge, E, n);
    k_coef<<<cdiv(n, 256), 256>>>(n);

    // CSR (by dst) — built once, used by all 3 layers
    k_scan1<<<nb, SCANB>>>(n);
    k_scan2<<<1, 1>>>(n, nb);
    k_scan3<<<nb, SCANB>>>(n);
    k_fill<<<cdiv(E, 256), 256>>>(edge, E);

    // Layer 1
    k_scale<<<cdiv(n * DV4, 256), 256>>>(node_attr, n);
    k_gather<<<cdiv(n * 32, 256), 256>>>(n);
    k_gemm<true><<<cdiv(n, 64), 128>>>(W0, b0, nullptr, n);
    // Layer 2
    k_gather<<<cdiv(n * 32, 256), 256>>>(n);
    k_gemm<true><<<cdiv(n, 64), 128>>>(W1, b1, nullptr, n);
    // Layer 3
    k_gather<<<cdiv(n * 32, 256), 256>>>(n);
    k_gemm<false><<<cdiv(n, 64), 128>>>(W2, b2, (float*)d_out, n);
}

// round 5
// speedup vs baseline: 2.1065x; 1.2781x over previous
#include <cuda_runtime.h>
#include <math.h>
#include <stdint.h>

// Problem constants (fixed by the dataset)
#define NMAX   100032
#define EMAX   1600000
#define DIMF   128        // feature dim = hidden dim
#define DV4    32         // DIMF/4
#define SCANB  1024
#define NSCANB ((NMAX + SCANB - 1) / SCANB)

// Static scratch (no allocation allowed)
__device__ float g_scaled[NMAX * DIMF];
__device__ float g_agg[NMAX * DIMF];
__device__ float g_csrc[NMAX];
__device__ float g_cdst[NMAX];
__device__ int   g_deg[2 * NMAX];     // [0..n) out-deg(+self), [n..2n) in-deg(+self)
__device__ int   g_off[NMAX + 1];     // CSR row offsets (by dst)
__device__ int   g_cursor[NMAX];      // fill cursors
__device__ int   g_csr_src[EMAX];     // CSR: src ids grouped by dst
__device__ int   g_bsum[NSCANB];      // scan block sums

static inline int cdiv(int a, int b) { return (a + b - 1) / b; }

// ---------------------------------------------------------------------------
// Degrees (self-loop included via init=1) and normalization coefficients
// ---------------------------------------------------------------------------
__global__ void k_deg_init(int n) {
    int i = blockIdx.x * blockDim.x + threadIdx.x;
    if (i < 2 * n) g_deg[i] = 1;
}

__global__ void k_deg_count(const int* __restrict__ ei, int E, int n) {
    int i = blockIdx.x * blockDim.x + threadIdx.x;
    if (i < E) {
        atomicAdd(&g_deg[ei[i]], 1);          // src -> out-degree
        atomicAdd(&g_deg[n + ei[E + i]], 1);  // dst -> in-degree
    }
}

__global__ void k_coef(int n) {
    int i = blockIdx.x * blockDim.x + threadIdx.x;
    if (i < n) {
        g_csrc[i] = rsqrtf((float)g_deg[i]);
        g_cdst[i] = rsqrtf((float)g_deg[n + i]);
    }
}

// ---------------------------------------------------------------------------
// CSR build: exclusive scan of raw in-degree (= g_deg[n+i]-1), then fill.
// ---------------------------------------------------------------------------
__global__ void k_scan1(int n) {
    __shared__ int sh[SCANB];
    int t = threadIdx.x;
    int i = blockIdx.x * SCANB + t;
    int v = (i < n) ? (g_deg[n + i] - 1) : 0;
    sh[t] = v;
    __syncthreads();
#pragma unroll
    for (int o = 1; o < SCANB; o <<= 1) {
        int add = (t >= o) ? sh[t - o] : 0;
        __syncthreads();
        sh[t] += add;
        __syncthreads();
    }
    if (i < n) g_off[i] = sh[t] - v;          // exclusive within block
    if (t == SCANB - 1) g_bsum[blockIdx.x] = sh[t];
}

__global__ void k_scan2(int n, int nb) {
    int run = 0;
    for (int b = 0; b < nb; b++) {
        int s = g_bsum[b];
        g_bsum[b] = run;
        run += s;
    }
    g_off[n] = run;   // == E
}

__global__ void k_scan3(int n) {
    int i = blockIdx.x * SCANB + threadIdx.x;
    if (i < n) {
        int o = g_off[i] + g_bsum[blockIdx.x];
        g_off[i] = o;
        g_cursor[i] = o;
    }
}

__global__ void k_fill(const int* __restrict__ ei, int E) {
    int i = blockIdx.x * blockDim.x + threadIdx.x;
    if (i < E) {
        int s = ei[i];
        int d = ei[E + i];
        int pos = atomicAdd(&g_cursor[d], 1);
        g_csr_src[pos] = s;
    }
}

// ---------------------------------------------------------------------------
// Layer-1 scale: scaled = node_attr * c_src[row]
// ---------------------------------------------------------------------------
__global__ void k_scale(const float* __restrict__ x, int n) {
    int idx = blockIdx.x * blockDim.x + threadIdx.x;
    if (idx < n * DV4) {
        int row = idx >> 5;
        float c = g_csrc[row];
        float4 v = ((const float4*)x)[idx];
        v.x *= c; v.y *= c; v.z *= c; v.w *= c;
        ((float4*)g_scaled)[idx] = v;
    }
}

// ---------------------------------------------------------------------------
// Gather-sum: agg[d,:] = scaled[d,:] + sum_{s in in(d)} scaled[s,:]
// One warp per dst node; lane = one float4 column.
// ---------------------------------------------------------------------------
__global__ void k_gather(int n) {
    int gw = (blockIdx.x * blockDim.x + threadIdx.x) >> 5;
    int lane = threadIdx.x & 31;
    if (gw >= n) return;

    const float4* sc = (const float4*)g_scaled;
    float4 acc = __ldg(&sc[gw * DV4 + lane]);   // self loop

    int j   = g_off[gw];
    int end = g_off[gw + 1];

    for (; j + 4 <= end; j += 4) {
        int s0 = __ldg(&g_csr_src[j]);
        int s1 = __ldg(&g_csr_src[j + 1]);
        int s2 = __ldg(&g_csr_src[j + 2]);
        int s3 = __ldg(&g_csr_src[j + 3]);
        float4 v0 = __ldg(&sc[s0 * DV4 + lane]);
        float4 v1 = __ldg(&sc[s1 * DV4 + lane]);
        float4 v2 = __ldg(&sc[s2 * DV4 + lane]);
        float4 v3 = __ldg(&sc[s3 * DV4 + lane]);
        acc.x += v0.x + v1.x + v2.x + v3.x;
        acc.y += v0.y + v1.y + v2.y + v3.y;
        acc.z += v0.z + v1.z + v2.z + v3.z;
        acc.w += v0.w + v1.w + v2.w + v3.w;
    }
    for (; j < end; j++) {
        int s = __ldg(&g_csr_src[j]);
        float4 v = __ldg(&sc[s * DV4 + lane]);
        acc.x += v.x; acc.y += v.y; acc.z += v.z; acc.w += v.w;
    }
    ((float4*)g_agg)[gw * DV4 + lane] = acc;
}

// ---------------------------------------------------------------------------
// Tensor-core GEMM (split TF32, fp32-accurate):
//   y[r,:] = (agg[r,:] * c_dst[r]) @ W + b
//   WRITE_SCALED: g_scaled[r,:] = relu(y) * c_src[r]   (hidden layers)
//   else:         out[r,:] = y                          (final layer)
// Block: 256 threads (8 warps), tile 128 rows x 128 cols.
// Warp w owns rows [w*16, w*16+16). K staged in 8 chunks of 16.
// 3 mma per tile: Ah*Bh + Al*Bh + Ah*Bl  (Al*Bl dropped, ~2^-24)
// ---------------------------------------------------------------------------
#define SA 20    // A smem row stride (floats): bank = 20g+t4 -> conflict-free
#define SB 136   // B smem row stride (floats): bank = 8*t4+g -> conflict-free

__device__ __forceinline__ void split_tf32(float x, float& hi, float& lo) {
    uint32_t h;
    asm("cvt.rna.tf32.f32 %0, %1;" : "=r"(h) : "f"(x));
    hi = __uint_as_float(h);
    float l = x - hi;         // exact (hi zeroes low mantissa bits)
    uint32_t l32;
    asm("cvt.rna.tf32.f32 %0, %1;" : "=r"(l32) : "f"(l));
    lo = __uint_as_float(l32);
}

__device__ __forceinline__ void mma_tf32(float* c, const uint32_t* a,
                                         uint32_t b0, uint32_t b1) {
    asm volatile(
        "mma.sync.aligned.m16n8k8.row.col.f32.tf32.tf32.f32 "
        "{%0,%1,%2,%3}, {%4,%5,%6,%7}, {%8,%9}, {%0,%1,%2,%3};"
        : "+f"(c[0]), "+f"(c[1]), "+f"(c[2]), "+f"(c[3])
        : "r"(a[0]), "r"(a[1]), "r"(a[2]), "r"(a[3]), "r"(b0), "r"(b1));
}

template <bool WRITE_SCALED>
__global__ void __launch_bounds__(256)
k_gemm_tc(const float* __restrict__ W, const float* __restrict__ b,
          float* __restrict__ out, int n) {
    __shared__ float Ah[128 * SA], Al[128 * SA];   // 128 rows x 16 k
    __shared__ float Bh[16 * SB],  Bl[16 * SB];    // 16 k x 128 cols

    const int tid  = threadIdx.x;
    const int warp = tid >> 5;
    const int lane = tid & 31;
    const int g    = lane >> 2;       // group id (0..7)
    const int t4   = lane & 3;        // thread in group
    const int rowBase = blockIdx.x * 128;
    const int warpRow = warp * 16;

    // acc[nt][0..3]; init with bias (d0:col=2*t4, d1:+1, d2/d3 same cols row+8)
    float acc[16][4];
#pragma unroll
    for (int nt = 0; nt < 16; nt++) {
        float b0v = __ldg(&b[nt * 8 + t4 * 2]);
        float b1v = __ldg(&b[nt * 8 + t4 * 2 + 1]);
        acc[nt][0] = b0v; acc[nt][1] = b1v;
        acc[nt][2] = b0v; acc[nt][3] = b1v;
    }

    for (int kc = 0; kc < 8; kc++) {
        __syncthreads();
        // ---- load A chunk: 128 rows x 16 k (x c_dst, split hi/lo) ----
        {
            int i = tid;                 // 512 float4 total, 2 per thread
#pragma unroll
            for (int it = 0; it < 2; it++, i += 256) {
                int r  = i >> 2;         // 0..127
                int c4 = i & 3;          // 0..3
                int gr = rowBase + r;
                float4 v = make_float4(0.f, 0.f, 0.f, 0.f);
                if (gr < n) {
                    v = ((const float4*)g_agg)[gr * DV4 + kc * 4 + c4];
                    float cd = g_cdst[gr];
                    v.x *= cd; v.y *= cd; v.z *= cd; v.w *= cd;
                }
                float* ph = &Ah[r * SA + c4 * 4];
                float* pl = &Al[r * SA + c4 * 4];
                split_tf32(v.x, ph[0], pl[0]);
                split_tf32(v.y, ph[1], pl[1]);
                split_tf32(v.z, ph[2], pl[2]);
                split_tf32(v.w, ph[3], pl[3]);
            }
        }
        // ---- load B chunk: 16 k-rows x 128 cols of W (split hi/lo) ----
        {
            int i = tid;
#pragma unroll
            for (int it = 0; it < 2; it++, i += 256) {
                int r  = i >> 5;         // 0..15
                int c4 = i & 31;         // 0..31
                float4 v = ((const float4*)W)[(kc * 16 + r) * DV4 + c4];
                float* ph = &Bh[r * SB + c4 * 4];
                float* pl = &Bl[r * SB + c4 * 4];
                split_tf32(v.x, ph[0], pl[0]);
                split_tf32(v.y, ph[1], pl[1]);
                split_tf32(v.z, ph[2], pl[2]);
                split_tf32(v.w, ph[3], pl[3]);
            }
        }
        __syncthreads();

#pragma unroll
        for (int ks = 0; ks < 2; ks++) {
            const int kb = ks * 8;
            // A fragments (m16k8): a0:(g,t4) a1:(g+8,t4) a2:(g,t4+4) a3:(g+8,t4+4)
            uint32_t ah[4], al[4];
            {
                const int r0 = (warpRow + g) * SA + kb + t4;
                const int r1 = (warpRow + g + 8) * SA + kb + t4;
                ah[0] = __float_as_uint(Ah[r0]);
                ah[1] = __float_as_uint(Ah[r1]);
                ah[2] = __float_as_uint(Ah[r0 + 4]);
                ah[3] = __float_as_uint(Ah[r1 + 4]);
                al[0] = __float_as_uint(Al[r0]);
                al[1] = __float_as_uint(Al[r1]);
                al[2] = __float_as_uint(Al[r0 + 4]);
                al[3] = __float_as_uint(Al[r1 + 4]);
            }
#pragma unroll
            for (int nt = 0; nt < 16; nt++) {
                // B fragments (k8n8 col): b0:(t4, g)  b1:(t4+4, g)
                const int o0 = (kb + t4) * SB + nt * 8 + g;
                const int o1 = (kb + t4 + 4) * SB + nt * 8 + g;
                uint32_t bh0 = __float_as_uint(Bh[o0]);
                uint32_t bh1 = __float_as_uint(Bh[o1]);
                uint32_t bl0 = __float_as_uint(Bl[o0]);
                uint32_t bl1 = __float_as_uint(Bl[o1]);
                mma_tf32(acc[nt], ah, bh0, bh1);
                mma_tf32(acc[nt], al, bh0, bh1);
                mma_tf32(acc[nt], ah, bl0, bl1);
            }
        }
    }

    // ---- epilogue ----
    const int r0 = rowBase + warpRow + g;
    const int r1 = r0 + 8;
#pragma unroll
    for (int nt = 0; nt < 16; nt++) {
        const int col = nt * 8 + t4 * 2;
        if (WRITE_SCALED) {
            if (r0 < n) {
                float cs = g_csrc[r0];
                float2 o = make_float2(fmaxf(acc[nt][0], 0.f) * cs,
                                       fmaxf(acc[nt][1], 0.f) * cs);
                *(float2*)&g_scaled[r0 * DIMF + col] = o;
            }
            if (r1 < n) {
                float cs = g_csrc[r1];
                float2 o = make_float2(fmaxf(acc[nt][2], 0.f) * cs,
                                       fmaxf(acc[nt][3], 0.f) * cs);
                *(float2*)&g_scaled[r1 * DIMF + col] = o;
            }
        } else {
            if (r0 < n)
                *(float2*)&out[r0 * DIMF + col] = make_float2(acc[nt][0], acc[nt][1]);
            if (r1 < n)
                *(float2*)&out[r1 * DIMF + col] = make_float2(acc[nt][2], acc[nt][3]);
        }
    }
}

// ---------------------------------------------------------------------------

extern "C" void kernel_launch(void* const* d_in, const int* in_sizes, int n_in,
                              void* d_out, int out_size) {
    const float* node_attr = (const float*)d_in[0];
    const float* W0 = (const float*)d_in[1];
    const float* b0 = (const float*)d_in[2];
    const float* W1 = (const float*)d_in[3];
    const float* b1 = (const float*)d_in[4];
    const float* W2 = (const float*)d_in[5];
    const float* b2 = (const float*)d_in[6];
    const int*   edge = (const int*)d_in[7];

    int n = in_sizes[0] / DIMF;   // 100000
    int E = in_sizes[7] / 2;      // 1600000
    int nb = cdiv(n, SCANB);

    // degrees + coefficients
    k_deg_init<<<cdiv(2 * n, 256), 256>>>(n);
    k_deg_count<<<cdiv(E, 256), 256>>>(edge, E, n);
    k_coef<<<cdiv(n, 256), 256>>>(n);

    // CSR (by dst) — built once, used by all 3 layers
    k_scan1<<<nb, SCANB>>>(n);
    k_scan2<<<1, 1>>>(n, nb);
    k_scan3<<<nb, SCANB>>>(n);
    k_fill<<<cdiv(E, 256), 256>>>(edge, E);

    int gemmGrid = cdiv(n, 128);

    // Layer 1
    k_scale<<<cdiv(n * DV4, 256), 256>>>(node_attr, n);
    k_gather<<<cdiv(n * 32, 256), 256>>>(n);
    k_gemm_tc<true><<<gemmGrid, 256>>>(W0, b0, nullptr, n);
    // Layer 2
    k_gather<<<cdiv(n * 32, 256), 256>>>(n);
    k_gemm_tc<true><<<gemmGrid, 256>>>(W1, b1, nullptr, n);
    // Layer 3
    k_gather<<<cdiv(n * 32, 256), 256>>>(n);
    k_gemm_tc<false><<<gemmGrid, 256>>>(W2, b2, (float*)d_out, n);
}

// round 6
// speedup vs baseline: 2.3821x; 1.1308x over previous
#include <cuda_runtime.h>
#include <cuda_fp16.h>
#include <math.h>
#include <stdint.h>

// Problem constants (fixed by the dataset)
#define NMAX   100032
#define EMAX   1600000
#define DIMF   128        // feature dim = hidden dim
#define DV4    32         // DIMF/4
#define SCANB  1024
#define NSCANB ((NMAX + SCANB - 1) / SCANB)

// Static scratch (no allocation allowed)
__device__ __half2 g_scaled_h[NMAX * 64];   // scaled features, fp16 (gather table)
__device__ float   g_agg[NMAX * DIMF];      // aggregation result, fp32
__device__ float   g_csrc[NMAX];
__device__ float   g_cdst[NMAX];
__device__ int     g_deg[2 * NMAX];   // [0..n) out-deg(+self), [n..2n) in-deg(+self)
__device__ int     g_off[NMAX + 1];   // CSR row offsets (by dst)
__device__ int     g_cursor[NMAX];
__device__ int     g_csr_src[EMAX];   // CSR: src ids grouped by dst
__device__ int     g_bsum[NSCANB];

static inline int cdiv(int a, int b) { return (a + b - 1) / b; }

// ---------------------------------------------------------------------------
// Degrees (self-loop included via init=1) and normalization coefficients
// ---------------------------------------------------------------------------
__global__ void k_deg_init(int n) {
    int i = blockIdx.x * blockDim.x + threadIdx.x;
    if (i < 2 * n) g_deg[i] = 1;
}

__global__ void k_deg_count(const int* __restrict__ ei, int E, int n) {
    int i = blockIdx.x * blockDim.x + threadIdx.x;
    if (i < E) {
        atomicAdd(&g_deg[ei[i]], 1);          // src -> out-degree
        atomicAdd(&g_deg[n + ei[E + i]], 1);  // dst -> in-degree
    }
}

__global__ void k_coef(int n) {
    int i = blockIdx.x * blockDim.x + threadIdx.x;
    if (i < n) {
        g_csrc[i] = rsqrtf((float)g_deg[i]);
        g_cdst[i] = rsqrtf((float)g_deg[n + i]);
    }
}

// ---------------------------------------------------------------------------
// CSR build: exclusive scan of raw in-degree (= g_deg[n+i]-1), then fill.
// ---------------------------------------------------------------------------
__global__ void k_scan1(int n) {
    __shared__ int sh[SCANB];
    int t = threadIdx.x;
    int i = blockIdx.x * SCANB + t;
    int v = (i < n) ? (g_deg[n + i] - 1) : 0;
    sh[t] = v;
    __syncthreads();
#pragma unroll
    for (int o = 1; o < SCANB; o <<= 1) {
        int add = (t >= o) ? sh[t - o] : 0;
        __syncthreads();
        sh[t] += add;
        __syncthreads();
    }
    if (i < n) g_off[i] = sh[t] - v;
    if (t == SCANB - 1) g_bsum[blockIdx.x] = sh[t];
}

__global__ void k_scan2(int n, int nb) {
    int run = 0;
    for (int b = 0; b < nb; b++) {
        int s = g_bsum[b];
        g_bsum[b] = run;
        run += s;
    }
    g_off[n] = run;
}

__global__ void k_scan3(int n) {
    int i = blockIdx.x * SCANB + threadIdx.x;
    if (i < n) {
        int o = g_off[i] + g_bsum[blockIdx.x];
        g_off[i] = o;
        g_cursor[i] = o;
    }
}

__global__ void k_fill(const int* __restrict__ ei, int E) {
    int i = blockIdx.x * blockDim.x + threadIdx.x;
    if (i < E) {
        int s = ei[i];
        int d = ei[E + i];
        int pos = atomicAdd(&g_cursor[d], 1);
        g_csr_src[pos] = s;
    }
}

// ---------------------------------------------------------------------------
// Layer-1 scale: g_scaled_h = fp16(node_attr * c_src[row])
// One thread per 4 floats -> one uint2 (4 halves).
// ---------------------------------------------------------------------------
__global__ void k_scale(const float* __restrict__ x, int n) {
    int idx = blockIdx.x * blockDim.x + threadIdx.x;
    if (idx < n * DV4) {
        int row = idx >> 5;
        float c = g_csrc[row];
        float4 v = ((const float4*)x)[idx];
        __half2 h0 = __floats2half2_rn(v.x * c, v.y * c);
        __half2 h1 = __floats2half2_rn(v.z * c, v.w * c);
        uint2 o;
        o.x = *(uint32_t*)&h0;
        o.y = *(uint32_t*)&h1;
        ((uint2*)g_scaled_h)[idx] = o;
    }
}

// ---------------------------------------------------------------------------
// Gather-sum: agg[d,:] = scaled[d,:] + sum_{s in in(d)} scaled[s,:]
// fp16 table, fp32 accumulation. One warp per dst node; lane = 4 halves (8B),
// so one coalesced 256B warp access per edge row.
// ---------------------------------------------------------------------------
__device__ __forceinline__ float4 h4f(uint2 u) {
    float2 a = __half22float2(*(__half2*)&u.x);
    float2 b = __half22float2(*(__half2*)&u.y);
    return make_float4(a.x, a.y, b.x, b.y);
}

__global__ void k_gather(int n) {
    int gw = (blockIdx.x * blockDim.x + threadIdx.x) >> 5;
    int lane = threadIdx.x & 31;
    if (gw >= n) return;

    const uint2* sc = (const uint2*)g_scaled_h;
    float4 acc = h4f(__ldg(&sc[gw * 32 + lane]));   // self loop

    int j   = g_off[gw];
    int end = g_off[gw + 1];

    for (; j + 4 <= end; j += 4) {
        int s0 = __ldg(&g_csr_src[j]);
        int s1 = __ldg(&g_csr_src[j + 1]);
        int s2 = __ldg(&g_csr_src[j + 2]);
        int s3 = __ldg(&g_csr_src[j + 3]);
        float4 v0 = h4f(__ldg(&sc[s0 * 32 + lane]));
        float4 v1 = h4f(__ldg(&sc[s1 * 32 + lane]));
        float4 v2 = h4f(__ldg(&sc[s2 * 32 + lane]));
        float4 v3 = h4f(__ldg(&sc[s3 * 32 + lane]));
        acc.x += v0.x + v1.x + v2.x + v3.x;
        acc.y += v0.y + v1.y + v2.y + v3.y;
        acc.z += v0.z + v1.z + v2.z + v3.z;
        acc.w += v0.w + v1.w + v2.w + v3.w;
    }
    for (; j < end; j++) {
        int s = __ldg(&g_csr_src[j]);
        float4 v = h4f(__ldg(&sc[s * 32 + lane]));
        acc.x += v.x; acc.y += v.y; acc.z += v.z; acc.w += v.w;
    }
    ((float4*)g_agg)[gw * DV4 + lane] = acc;
}

// ---------------------------------------------------------------------------
// Tensor-core GEMM (split TF32, fp32-accurate):
//   y[r,:] = (agg[r,:] * c_dst[r]) @ W + b
//   WRITE_SCALED: g_scaled_h[r,:] = fp16(relu(y) * c_src[r])  (hidden layers)
//   else:         out[r,:] = y                                 (final layer)
// Block: 256 threads (8 warps), tile 128x128. 3 mma per tile (Al*Bl dropped).
// ---------------------------------------------------------------------------
#define SA 20    // A smem row stride (floats): conflict-free fragment reads
#define SB 136   // B smem row stride (floats): conflict-free fragment reads

__device__ __forceinline__ void split_tf32(float x, float& hi, float& lo) {
    uint32_t h;
    asm("cvt.rna.tf32.f32 %0, %1;" : "=r"(h) : "f"(x));
    hi = __uint_as_float(h);
    float l = x - hi;
    uint32_t l32;
    asm("cvt.rna.tf32.f32 %0, %1;" : "=r"(l32) : "f"(l));
    lo = __uint_as_float(l32);
}

__device__ __forceinline__ void mma_tf32(float* c, const uint32_t* a,
                                         uint32_t b0, uint32_t b1) {
    asm volatile(
        "mma.sync.aligned.m16n8k8.row.col.f32.tf32.tf32.f32 "
        "{%0,%1,%2,%3}, {%4,%5,%6,%7}, {%8,%9}, {%0,%1,%2,%3};"
        : "+f"(c[0]), "+f"(c[1]), "+f"(c[2]), "+f"(c[3])
        : "r"(a[0]), "r"(a[1]), "r"(a[2]), "r"(a[3]), "r"(b0), "r"(b1));
}

template <bool WRITE_SCALED>
__global__ void __launch_bounds__(256)
k_gemm_tc(const float* __restrict__ W, const float* __restrict__ b,
          float* __restrict__ out, int n) {
    __shared__ float Ah[128 * SA], Al[128 * SA];   // 128 rows x 16 k
    __shared__ float Bh[16 * SB],  Bl[16 * SB];    // 16 k x 128 cols

    const int tid  = threadIdx.x;
    const int warp = tid >> 5;
    const int lane = tid & 31;
    const int g    = lane >> 2;
    const int t4   = lane & 3;
    const int rowBase = blockIdx.x * 128;
    const int warpRow = warp * 16;

    float acc[16][4];
#pragma unroll
    for (int nt = 0; nt < 16; nt++) {
        float b0v = __ldg(&b[nt * 8 + t4 * 2]);
        float b1v = __ldg(&b[nt * 8 + t4 * 2 + 1]);
        acc[nt][0] = b0v; acc[nt][1] = b1v;
        acc[nt][2] = b0v; acc[nt][3] = b1v;
    }

    for (int kc = 0; kc < 8; kc++) {
        __syncthreads();
        // ---- A chunk: 128 rows x 16 k (x c_dst, split hi/lo) ----
        {
            int i = tid;
#pragma unroll
            for (int it = 0; it < 2; it++, i += 256) {
                int r  = i >> 2;
                int c4 = i & 3;
                int gr = rowBase + r;
                float4 v = make_float4(0.f, 0.f, 0.f, 0.f);
                if (gr < n) {
                    v = ((const float4*)g_agg)[gr * DV4 + kc * 4 + c4];
                    float cd = g_cdst[gr];
                    v.x *= cd; v.y *= cd; v.z *= cd; v.w *= cd;
                }
                float* ph = &Ah[r * SA + c4 * 4];
                float* pl = &Al[r * SA + c4 * 4];
                split_tf32(v.x, ph[0], pl[0]);
                split_tf32(v.y, ph[1], pl[1]);
                split_tf32(v.z, ph[2], pl[2]);
                split_tf32(v.w, ph[3], pl[3]);
            }
        }
        // ---- B chunk: 16 k-rows x 128 cols of W (split hi/lo) ----
        {
            int i = tid;
#pragma unroll
            for (int it = 0; it < 2; it++, i += 256) {
                int r  = i >> 5;
                int c4 = i & 31;
                float4 v = ((const float4*)W)[(kc * 16 + r) * DV4 + c4];
                float* ph = &Bh[r * SB + c4 * 4];
                float* pl = &Bl[r * SB + c4 * 4];
                split_tf32(v.x, ph[0], pl[0]);
                split_tf32(v.y, ph[1], pl[1]);
                split_tf32(v.z, ph[2], pl[2]);
                split_tf32(v.w, ph[3], pl[3]);
            }
        }
        __syncthreads();

#pragma unroll
        for (int ks = 0; ks < 2; ks++) {
            const int kb = ks * 8;
            uint32_t ah[4], al[4];
            {
                const int r0 = (warpRow + g) * SA + kb + t4;
                const int r1 = (warpRow + g + 8) * SA + kb + t4;
                ah[0] = __float_as_uint(Ah[r0]);
                ah[1] = __float_as_uint(Ah[r1]);
                ah[2] = __float_as_uint(Ah[r0 + 4]);
                ah[3] = __float_as_uint(Ah[r1 + 4]);
                al[0] = __float_as_uint(Al[r0]);
                al[1] = __float_as_uint(Al[r1]);
                al[2] = __float_as_uint(Al[r0 + 4]);
                al[3] = __float_as_uint(Al[r1 + 4]);
            }
#pragma unroll
            for (int nt = 0; nt < 16; nt++) {
                const int o0 = (kb + t4) * SB + nt * 8 + g;
                const int o1 = (kb + t4 + 4) * SB + nt * 8 + g;
                uint32_t bh0 = __float_as_uint(Bh[o0]);
                uint32_t bh1 = __float_as_uint(Bh[o1]);
                uint32_t bl0 = __float_as_uint(Bl[o0]);
                uint32_t bl1 = __float_as_uint(Bl[o1]);
                mma_tf32(acc[nt], ah, bh0, bh1);
                mma_tf32(acc[nt], al, bh0, bh1);
                mma_tf32(acc[nt], ah, bl0, bl1);
            }
        }
    }

    // ---- epilogue ----
    const int r0 = rowBase + warpRow + g;
    const int r1 = r0 + 8;
#pragma unroll
    for (int nt = 0; nt < 16; nt++) {
        const int col = nt * 8 + t4 * 2;
        if (WRITE_SCALED) {
            if (r0 < n) {
                float cs = g_csrc[r0];
                g_scaled_h[r0 * 64 + (col >> 1)] =
                    __floats2half2_rn(fmaxf(acc[nt][0], 0.f) * cs,
                                      fmaxf(acc[nt][1], 0.f) * cs);
            }
            if (r1 < n) {
                float cs = g_csrc[r1];
                g_scaled_h[r1 * 64 + (col >> 1)] =
                    __floats2half2_rn(fmaxf(acc[nt][2], 0.f) * cs,
                                      fmaxf(acc[nt][3], 0.f) * cs);
            }
        } else {
            if (r0 < n)
                *(float2*)&out[r0 * DIMF + col] = make_float2(acc[nt][0], acc[nt][1]);
            if (r1 < n)
                *(float2*)&out[r1 * DIMF + col] = make_float2(acc[nt][2], acc[nt][3]);
        }
    }
}

// ---------------------------------------------------------------------------

extern "C" void kernel_launch(void* const* d_in, const int* in_sizes, int n_in,
                              void* d_out, int out_size) {
    const float* node_attr = (const float*)d_in[0];
    const float* W0 = (const float*)d_in[1];
    const float* b0 = (const float*)d_in[2];
    const float* W1 = (const float*)d_in[3];
    const float* b1 = (const float*)d_in[4];
    const float* W2 = (const float*)d_in[5];
    const float* b2 = (const float*)d_in[6];
    const int*   edge = (const int*)d_in[7];

    int n = in_sizes[0] / DIMF;   // 100000
    int E = in_sizes[7] / 2;      // 1600000
    int nb = cdiv(n, SCANB);

    // degrees + coefficients
    k_deg_init<<<cdiv(2 * n, 256), 256>>>(n);
    k_deg_count<<<cdiv(E, 256), 256>>>(edge, E, n);
    k_coef<<<cdiv(n, 256), 256>>>(n);

    // CSR (by dst) — built once, used by all 3 layers
    k_scan1<<<nb, SCANB>>>(n);
    k_scan2<<<1, 1>>>(n, nb);
    k_scan3<<<nb, SCANB>>>(n);
    k_fill<<<cdiv(E, 256), 256>>>(edge, E);

    int gemmGrid = cdiv(n, 128);

    // Layer 1
    k_scale<<<cdiv(n * DV4, 256), 256>>>(node_attr, n);
    k_gather<<<cdiv(n * 32, 256), 256>>>(n);
    k_gemm_tc<true><<<gemmGrid, 256>>>(W0, b0, nullptr, n);
    // Layer 2
    k_gather<<<cdiv(n * 32, 256), 256>>>(n);
    k_gemm_tc<true><<<gemmGrid, 256>>>(W1, b1, nullptr, n);
    // Layer 3
    k_gather<<<cdiv(n * 32, 256), 256>>>(n);
    k_gemm_tc<false><<<gemmGrid, 256>>>(W2, b2, (float*)d_out, n);
}

// round 7
// speedup vs baseline: 2.9243x; 1.2276x over previous
#include <cuda_runtime.h>
#include <cuda_fp16.h>
#include <math.h>
#include <stdint.h>

// Problem constants (fixed by the dataset)
#define NMAX   100032
#define EMAX   1600000
#define DIMF   128        // feature dim = hidden dim
#define DV4    32         // DIMF/4
#define SCANB  1024
#define NSCANB ((NMAX + SCANB - 1) / SCANB)

// Static scratch (no allocation allowed)
__device__ __half2 g_scaled_h[NMAX * 64];   // scaled features, fp16 (gather table)
__device__ float   g_agg[NMAX * DIMF];      // aggregation result, fp32
__device__ float   g_csrc[NMAX];
__device__ float   g_cdst[NMAX];
__device__ int     g_deg[2 * NMAX];   // [0..n) out-deg(+self), [n..2n) in-deg(+self)
__device__ int     g_off[NMAX + 1];   // CSR row offsets (by dst)
__device__ int     g_cursor[NMAX];
__device__ int     g_csr_src[EMAX];   // CSR: src ids grouped by dst
__device__ int     g_bsum[NSCANB];

static inline int cdiv(int a, int b) { return (a + b - 1) / b; }

// ---------------------------------------------------------------------------
// Degrees (self-loop included via init=1) and normalization coefficients
// ---------------------------------------------------------------------------
__global__ void k_deg_init(int n) {
    int i = blockIdx.x * blockDim.x + threadIdx.x;
    if (i < 2 * n) g_deg[i] = 1;
}

__global__ void k_deg_count(const int* __restrict__ ei, int E, int n) {
    int i = blockIdx.x * blockDim.x + threadIdx.x;
    if (i < E) {
        atomicAdd(&g_deg[ei[i]], 1);          // src -> out-degree
        atomicAdd(&g_deg[n + ei[E + i]], 1);  // dst -> in-degree
    }
}

__global__ void k_coef(int n) {
    int i = blockIdx.x * blockDim.x + threadIdx.x;
    if (i < n) {
        g_csrc[i] = rsqrtf((float)g_deg[i]);
        g_cdst[i] = rsqrtf((float)g_deg[n + i]);
    }
}

// ---------------------------------------------------------------------------
// CSR build: exclusive scan of raw in-degree (= g_deg[n+i]-1), then fill.
// ---------------------------------------------------------------------------
__global__ void k_scan1(int n) {
    __shared__ int sh[SCANB];
    int t = threadIdx.x;
    int i = blockIdx.x * SCANB + t;
    int v = (i < n) ? (g_deg[n + i] - 1) : 0;
    sh[t] = v;
    __syncthreads();
#pragma unroll
    for (int o = 1; o < SCANB; o <<= 1) {
        int add = (t >= o) ? sh[t - o] : 0;
        __syncthreads();
        sh[t] += add;
        __syncthreads();
    }
    if (i < n) g_off[i] = sh[t] - v;
    if (t == SCANB - 1) g_bsum[blockIdx.x] = sh[t];
}

__global__ void k_scan2(int n, int nb) {
    int run = 0;
    for (int b = 0; b < nb; b++) {
        int s = g_bsum[b];
        g_bsum[b] = run;
        run += s;
    }
    g_off[n] = run;
}

__global__ void k_scan3(int n) {
    int i = blockIdx.x * SCANB + threadIdx.x;
    if (i < n) {
        int o = g_off[i] + g_bsum[blockIdx.x];
        g_off[i] = o;
        g_cursor[i] = o;
    }
}

__global__ void k_fill(const int* __restrict__ ei, int E) {
    int i = blockIdx.x * blockDim.x + threadIdx.x;
    if (i < E) {
        int s = ei[i];
        int d = ei[E + i];
        int pos = atomicAdd(&g_cursor[d], 1);
        g_csr_src[pos] = s;
    }
}

// ---------------------------------------------------------------------------
// Layer-1 scale: g_scaled_h = fp16(node_attr * c_src[row])
// ---------------------------------------------------------------------------
__global__ void k_scale(const float* __restrict__ x, int n) {
    int idx = blockIdx.x * blockDim.x + threadIdx.x;
    if (idx < n * DV4) {
        int row = idx >> 5;
        float c = g_csrc[row];
        float4 v = ((const float4*)x)[idx];
        __half2 h0 = __floats2half2_rn(v.x * c, v.y * c);
        __half2 h1 = __floats2half2_rn(v.z * c, v.w * c);
        uint2 o;
        o.x = *(uint32_t*)&h0;
        o.y = *(uint32_t*)&h1;
        ((uint2*)g_scaled_h)[idx] = o;
    }
}

// ---------------------------------------------------------------------------
// Gather-sum: agg[d,:] = scaled[d,:] + sum_{s in in(d)} scaled[s,:]
// fp16 table, fp32 accumulation. One warp per dst node; lane = 4 halves (8B).
// ---------------------------------------------------------------------------
__device__ __forceinline__ float4 h4f(uint2 u) {
    float2 a = __half22float2(*(__half2*)&u.x);
    float2 b = __half22float2(*(__half2*)&u.y);
    return make_float4(a.x, a.y, b.x, b.y);
}

__global__ void k_gather(int n) {
    int gw = (blockIdx.x * blockDim.x + threadIdx.x) >> 5;
    int lane = threadIdx.x & 31;
    if (gw >= n) return;

    const uint2* sc = (const uint2*)g_scaled_h;
    float4 acc = h4f(__ldg(&sc[gw * 32 + lane]));   // self loop

    int j   = g_off[gw];
    int end = g_off[gw + 1];

    for (; j + 4 <= end; j += 4) {
        int s0 = __ldg(&g_csr_src[j]);
        int s1 = __ldg(&g_csr_src[j + 1]);
        int s2 = __ldg(&g_csr_src[j + 2]);
        int s3 = __ldg(&g_csr_src[j + 3]);
        float4 v0 = h4f(__ldg(&sc[s0 * 32 + lane]));
        float4 v1 = h4f(__ldg(&sc[s1 * 32 + lane]));
        float4 v2 = h4f(__ldg(&sc[s2 * 32 + lane]));
        float4 v3 = h4f(__ldg(&sc[s3 * 32 + lane]));
        acc.x += v0.x + v1.x + v2.x + v3.x;
        acc.y += v0.y + v1.y + v2.y + v3.y;
        acc.z += v0.z + v1.z + v2.z + v3.z;
        acc.w += v0.w + v1.w + v2.w + v3.w;
    }
    for (; j < end; j++) {
        int s = __ldg(&g_csr_src[j]);
        float4 v = h4f(__ldg(&sc[s * 32 + lane]));
        acc.x += v.x; acc.y += v.y; acc.z += v.z; acc.w += v.w;
    }
    ((float4*)g_agg)[gw * DV4 + lane] = acc;
}

// ---------------------------------------------------------------------------
// fp16 tensor-core GEMM (mma.m16n8k16, fp32 accumulate):
//   y[r,:] = (agg[r,:] * c_dst[r]) @ W + b
//   WRITE_SCALED: g_scaled_h[r,:] = fp16(relu(y) * c_src[r])  (hidden layers)
//   else:         out[r,:] = y                                 (final layer)
// Block: 256 threads (8 warps), tile 128x128, K staged in 2 chunks of 64.
// smem rows are 72 halves (36 words): fragment LDS bank = 4g+t4 -> conflict-free.
// ---------------------------------------------------------------------------
#define SROW 36   // smem row stride in 32-bit words (72 halves)

__device__ __forceinline__ void mma_f16(float* c, const uint32_t* a,
                                        uint32_t b0, uint32_t b1) {
    asm volatile(
        "mma.sync.aligned.m16n8k16.row.col.f32.f16.f16.f32 "
        "{%0,%1,%2,%3}, {%4,%5,%6,%7}, {%8,%9}, {%0,%1,%2,%3};"
        : "+f"(c[0]), "+f"(c[1]), "+f"(c[2]), "+f"(c[3])
        : "r"(a[0]), "r"(a[1]), "r"(a[2]), "r"(a[3]), "r"(b0), "r"(b1));
}

template <bool WRITE_SCALED>
__global__ void __launch_bounds__(256)
k_gemm_f16(const float* __restrict__ W, const float* __restrict__ b,
           float* __restrict__ out, int n) {
    __shared__ uint32_t As[128 * SROW];   // A tile: 128 rows x 64 k (fp16)
    __shared__ uint32_t Bs[128 * SROW];   // W^T tile: 128 n x 64 k (fp16)

    const int tid  = threadIdx.x;
    const int warp = tid >> 5;
    const int lane = tid & 31;
    const int g    = lane >> 2;       // 0..7
    const int t4   = lane & 3;        // 0..3
    const int rowBase = blockIdx.x * 128;
    const int warpRow = warp * 16;

    // acc init with bias: c0:(row g, col 2t4) c1:(g,2t4+1) c2:(g+8,2t4) c3:(g+8,2t4+1)
    float acc[16][4];
#pragma unroll
    for (int nt = 0; nt < 16; nt++) {
        float b0v = __ldg(&b[nt * 8 + t4 * 2]);
        float b1v = __ldg(&b[nt * 8 + t4 * 2 + 1]);
        acc[nt][0] = b0v; acc[nt][1] = b1v;
        acc[nt][2] = b0v; acc[nt][3] = b1v;
    }

#pragma unroll
    for (int kc2 = 0; kc2 < 2; kc2++) {
        __syncthreads();
        // ---- A chunk: 128 rows x 64 k, fp32 agg * c_dst -> fp16 ----
        for (int i = tid; i < 128 * 16; i += 256) {
            int r  = i >> 4;          // 0..127
            int c4 = i & 15;          // float4 index within 64-k chunk
            int gr = rowBase + r;
            float4 v = make_float4(0.f, 0.f, 0.f, 0.f);
            if (gr < n) {
                v = ((const float4*)g_agg)[gr * DV4 + kc2 * 16 + c4];
                float cd = g_cdst[gr];
                v.x *= cd; v.y *= cd; v.z *= cd; v.w *= cd;
            }
            __half2 h0 = __floats2half2_rn(v.x, v.y);
            __half2 h1 = __floats2half2_rn(v.z, v.w);
            ((uint2*)As)[r * (SROW / 2) + c4] =
                make_uint2(*(uint32_t*)&h0, *(uint32_t*)&h1);
        }
        // ---- W chunk transpose: W[k][n] (64 k-rows) -> Bs[n][k] fp16 ----
        for (int i = tid; i < 64 * 32; i += 256) {
            int k  = i >> 5;          // 0..63
            int c4 = i & 31;          // n0 = c4*4
            float4 v = ((const float4*)W)[(kc2 * 64 + k) * DV4 + c4];
            __half* bh = (__half*)Bs;
            int n0 = c4 * 4;
            bh[(n0 + 0) * 2 * SROW + k] = __float2half_rn(v.x);
            bh[(n0 + 1) * 2 * SROW + k] = __float2half_rn(v.y);
            bh[(n0 + 2) * 2 * SROW + k] = __float2half_rn(v.z);
            bh[(n0 + 3) * 2 * SROW + k] = __float2half_rn(v.w);
        }
        __syncthreads();

#pragma unroll
        for (int kc = 0; kc < 4; kc++) {
            // A frags: a0:(g, 2t4) a1:(g+8, 2t4) a2:(g, 2t4+8) a3:(g+8, 2t4+8)
            uint32_t a[4];
            const int a0 = (warpRow + g) * SROW + kc * 8 + t4;
            const int a1 = a0 + 8 * SROW;
            a[0] = As[a0];
            a[1] = As[a1];
            a[2] = As[a0 + 4];
            a[3] = As[a1 + 4];
#pragma unroll
            for (int nt = 0; nt < 16; nt++) {
                // B frags (col-major k16n8): b0:(2t4, g) b1:(2t4+8, g), n = nt*8+g
                const int bo = (nt * 8 + g) * SROW + kc * 8 + t4;
                mma_f16(acc[nt], a, Bs[bo], Bs[bo + 4]);
            }
        }
    }

    // ---- epilogue ----
    const int r0 = rowBase + warpRow + g;
    const int r1 = r0 + 8;
#pragma unroll
    for (int nt = 0; nt < 16; nt++) {
        const int col = nt * 8 + t4 * 2;
        if (WRITE_SCALED) {
            if (r0 < n) {
                float cs = g_csrc[r0];
                g_scaled_h[r0 * 64 + (col >> 1)] =
                    __floats2half2_rn(fmaxf(acc[nt][0], 0.f) * cs,
                                      fmaxf(acc[nt][1], 0.f) * cs);
            }
            if (r1 < n) {
                float cs = g_csrc[r1];
                g_scaled_h[r1 * 64 + (col >> 1)] =
                    __floats2half2_rn(fmaxf(acc[nt][2], 0.f) * cs,
                                      fmaxf(acc[nt][3], 0.f) * cs);
            }
        } else {
            if (r0 < n)
                *(float2*)&out[r0 * DIMF + col] = make_float2(acc[nt][0], acc[nt][1]);
            if (r1 < n)
                *(float2*)&out[r1 * DIMF + col] = make_float2(acc[nt][2], acc[nt][3]);
        }
    }
}

// ---------------------------------------------------------------------------

extern "C" void kernel_launch(void* const* d_in, const int* in_sizes, int n_in,
                              void* d_out, int out_size) {
    const float* node_attr = (const float*)d_in[0];
    const float* W0 = (const float*)d_in[1];
    const float* b0 = (const float*)d_in[2];
    const float* W1 = (const float*)d_in[3];
    const float* b1 = (const float*)d_in[4];
    const float* W2 = (const float*)d_in[5];
    const float* b2 = (const float*)d_in[6];
    const int*   edge = (const int*)d_in[7];

    int n = in_sizes[0] / DIMF;   // 100000
    int E = in_sizes[7] / 2;      // 1600000
    int nb = cdiv(n, SCANB);

    // degrees + coefficients
    k_deg_init<<<cdiv(2 * n, 256), 256>>>(n);
    k_deg_count<<<cdiv(E, 256), 256>>>(edge, E, n);
    k_coef<<<cdiv(n, 256), 256>>>(n);

    // CSR (by dst) — built once, used by all 3 layers
    k_scan1<<<nb, SCANB>>>(n);
    k_scan2<<<1, 1>>>(n, nb);
    k_scan3<<<nb, SCANB>>>(n);
    k_fill<<<cdiv(E, 256), 256>>>(edge, E);

    int gemmGrid = cdiv(n, 128);

    // Layer 1
    k_scale<<<cdiv(n * DV4, 256), 256>>>(node_attr, n);
    k_gather<<<cdiv(n * 32, 256), 256>>>(n);
    k_gemm_f16<true><<<gemmGrid, 256>>>(W0, b0, nullptr, n);
    // Layer 2
    k_gather<<<cdiv(n * 32, 256), 256>>>(n);
    k_gemm_f16<true><<<gemmGrid, 256>>>(W1, b1, nullptr, n);
    // Layer 3
    k_gather<<<cdiv(n * 32, 256), 256>>>(n);
    k_gemm_f16<false><<<gemmGrid, 256>>>(W2, b2, (float*)d_out, n);
}